// round 16
// baseline (speedup 1.0000x reference)
#include <cuda_runtime.h>
#include <cuda_fp16.h>

#define NN 100000
#define NE 3200000
#define NG 64
#define EPS 1e-5f

#define GDC_WAIT()   asm volatile("griddepcontrol.wait;" ::: "memory")
#define GDC_LAUNCH() asm volatile("griddepcontrol.launch_dependents;" ::: "memory")

// Scratch. d_a1 fully overwritten by node1 each run; d_m/d_n/d_degx/d_acc are
// accumulators reset by the last kernel that reads them.
__device__ float2 d_y2[NN];     // packed {half2 y01, half2 y23}  (8B gather)
__device__ float4 d_a1[NN];     // fp32 accumulator, seeded y_i by node1
__device__ float2 d_zp2[NN];    // packed {half2 z01, half2 z23}  (8B gather)
__device__ float4 d_m[NN];      // layer2 v4 accumulator (reset in node3)
__device__ float  d_n[NN];      // layer2 scalar accumulator (reset when used)
__device__ float  d_degx[NN];   // degree-1 (reset in node3)
__device__ float  d_dinv[NN];
__device__ double d_sum[4];     // reset in node2
__device__ double d_sumsq[4];   // reset in node2
__device__ int    d_needn;      // 1 iff conv1 bias b0 nonzero
__device__ float  d_acc[NG * 8];// per graph: [0..3]=s4,[4]=ss,[5]=ng; reset in final

__device__ __forceinline__ void red4(float4* p, float a, float b, float c, float d) {
    asm volatile("red.global.add.v4.f32 [%0], {%1,%2,%3,%4};"
                 :: "l"(p), "f"(a), "f"(b), "f"(c), "f"(d) : "memory");
}
__device__ __forceinline__ void red1(float* p, float a) {
    asm volatile("red.global.add.f32 [%0], %1;" :: "l"(p), "f"(a) : "memory");
}
__device__ __forceinline__ float4 unpack8(float2 g) {
    float2 lo = __half22float2(*reinterpret_cast<half2*>(&g.x));
    float2 hi = __half22float2(*reinterpret_cast<half2*>(&g.y));
    return make_float4(lo.x, lo.y, hi.x, hi.y);
}

// Fused: degree accumulation (8 edges/thread) + BN0 statistics
__global__ void __launch_bounds__(256) k_pre(const float* __restrict__ x,
                                             const int* __restrict__ ei) {
    int t = blockIdx.x * blockDim.x + threadIdx.x;
    if (t < NE / 8) {
        const int4* dp = (const int4*)(ei + NE);
        int4 d0 = __ldg(&dp[2 * t]);
        int4 d1 = __ldg(&dp[2 * t + 1]);
        red1(&d_degx[d0.x], 1.0f);
        red1(&d_degx[d0.y], 1.0f);
        red1(&d_degx[d0.z], 1.0f);
        red1(&d_degx[d0.w], 1.0f);
        red1(&d_degx[d1.x], 1.0f);
        red1(&d_degx[d1.y], 1.0f);
        red1(&d_degx[d1.z], 1.0f);
        red1(&d_degx[d1.w], 1.0f);
    }
    if (blockIdx.x < 256) {
        int j0 = blockIdx.x * blockDim.x + threadIdx.x;
        int stride = 256 * blockDim.x;
        double s0 = 0, s1 = 0, s2 = 0, s3 = 0;
        double q0 = 0, q1 = 0, q2 = 0, q3 = 0;
        for (int j = j0; j < NN; j += stride) {
            float4 v = ((const float4*)x)[j];
            s0 += v.x; q0 += (double)v.x * v.x;
            s1 += v.y; q1 += (double)v.y * v.y;
            s2 += v.z; q2 += (double)v.z * v.z;
            s3 += v.w; q3 += (double)v.w * v.w;
        }
        #pragma unroll
        for (int o = 16; o > 0; o >>= 1) {
            s0 += __shfl_down_sync(0xffffffffu, s0, o);
            s1 += __shfl_down_sync(0xffffffffu, s1, o);
            s2 += __shfl_down_sync(0xffffffffu, s2, o);
            s3 += __shfl_down_sync(0xffffffffu, s3, o);
            q0 += __shfl_down_sync(0xffffffffu, q0, o);
            q1 += __shfl_down_sync(0xffffffffu, q1, o);
            q2 += __shfl_down_sync(0xffffffffu, q2, o);
            q3 += __shfl_down_sync(0xffffffffu, q3, o);
        }
        if ((threadIdx.x & 31) == 0) {
            atomicAdd(&d_sum[0], s0); atomicAdd(&d_sumsq[0], q0);
            atomicAdd(&d_sum[1], s1); atomicAdd(&d_sumsq[1], q1);
            atomicAdd(&d_sum[2], s2); atomicAdd(&d_sumsq[2], q2);
            atomicAdd(&d_sum[3], s3); atomicAdd(&d_sumsq[3], q3);
        }
    }
    GDC_LAUNCH();
}

// BN0 normalize + dinv + packed y; seeds d_a1 = y; 2 nodes/thread
__global__ void __launch_bounds__(256) k_node1(const float* __restrict__ x,
                                               const float* __restrict__ g0,
                                               const float* __restrict__ b0,
                                               const float* __restrict__ b0c) {
    __shared__ float sbn[12];
    int t = blockIdx.x * blockDim.x + threadIdx.x;
    int i0 = 2 * t, i1 = 2 * t + 1;
    bool a0 = (i0 < NN), a1 = (i1 < NN);
    float4 v0 = a0 ? ((const float4*)x)[i0] : make_float4(0, 0, 0, 0);  // prelude
    float4 v1 = a1 ? ((const float4*)x)[i1] : make_float4(0, 0, 0, 0);  // prelude
    GDC_WAIT();
    if (threadIdx.x == 0) {
        #pragma unroll
        for (int c = 0; c < 4; c++) {
            double m = d_sum[c] / (double)NN;
            double var = d_sumsq[c] / (double)NN - m * m;
            sbn[c] = (float)m;
            sbn[4 + c] = rsqrtf((float)var + EPS) * g0[c];
            sbn[8 + c] = b0[c];
        }
        if (blockIdx.x == 0) {
            float mx = 0.f;
            for (int j = 0; j < 64; j++) mx = fmaxf(mx, fabsf(b0c[j]));
            d_needn = (mx > 0.f) ? 1 : 0;
        }
    }
    __syncthreads();
    float dg0 = a0 ? d_degx[i0] : 0.f;
    float dg1 = a1 ? d_degx[i1] : 0.f;
    if (a0) {
        float di = rsqrtf(dg0 + 1.0f);
        float4 y;
        y.x = ((v0.x - sbn[0]) * sbn[4] + sbn[8]) * di;
        y.y = ((v0.y - sbn[1]) * sbn[5] + sbn[9]) * di;
        y.z = ((v0.z - sbn[2]) * sbn[6] + sbn[10]) * di;
        y.w = ((v0.w - sbn[3]) * sbn[7] + sbn[11]) * di;
        d_dinv[i0] = di;
        half2 h01 = __floats2half2_rn(y.x, y.y);
        half2 h23 = __floats2half2_rn(y.z, y.w);
        float2 pk;
        pk.x = *reinterpret_cast<float*>(&h01);
        pk.y = *reinterpret_cast<float*>(&h23);
        d_y2[i0] = pk;
        d_a1[i0] = y;      // self-loop seed (fp32)
    }
    if (a1) {
        float di = rsqrtf(dg1 + 1.0f);
        float4 y;
        y.x = ((v1.x - sbn[0]) * sbn[4] + sbn[8]) * di;
        y.y = ((v1.y - sbn[1]) * sbn[5] + sbn[9]) * di;
        y.z = ((v1.z - sbn[2]) * sbn[6] + sbn[10]) * di;
        y.w = ((v1.w - sbn[3]) * sbn[7] + sbn[11]) * di;
        d_dinv[i1] = di;
        half2 h01 = __floats2half2_rn(y.x, y.y);
        half2 h23 = __floats2half2_rn(y.z, y.w);
        float2 pk;
        pk.x = *reinterpret_cast<float*>(&h01);
        pk.y = *reinterpret_cast<float*>(&h23);
        d_y2[i1] = pk;
        d_a1[i1] = y;
    }
    GDC_LAUNCH();
}

// a1[d] += y[s] (8B gathers, fp32 REDs), 8 edges/thread
__global__ void __launch_bounds__(256) k_edge1(const int* __restrict__ ei) {
    int t = blockIdx.x * blockDim.x + threadIdx.x;
    bool act = (t < NE / 8);
    int tt = act ? t : 0;
    const int4* sp = (const int4*)ei;
    const int4* dp = (const int4*)(ei + NE);
    int4 s0 = __ldg(&sp[2 * tt]), s1 = __ldg(&sp[2 * tt + 1]);
    int4 d0 = __ldg(&dp[2 * tt]), d1 = __ldg(&dp[2 * tt + 1]);
    GDC_WAIT();
    if (act) {
        float2 g0 = __ldg(&d_y2[s0.x]);
        float2 g1 = __ldg(&d_y2[s0.y]);
        float2 g2 = __ldg(&d_y2[s0.z]);
        float2 g3 = __ldg(&d_y2[s0.w]);
        float2 g4 = __ldg(&d_y2[s1.x]);
        float2 g5 = __ldg(&d_y2[s1.y]);
        float2 g6 = __ldg(&d_y2[s1.z]);
        float2 g7 = __ldg(&d_y2[s1.w]);
        #define E1_ONE(g, dd) do {                                  \
            float4 _y = unpack8(g);                                 \
            red4(&d_a1[dd], _y.x, _y.y, _y.z, _y.w);                \
        } while (0)
        E1_ONE(g0, d0.x);
        E1_ONE(g1, d0.y);
        E1_ONE(g2, d0.z);
        E1_ONE(g3, d0.w);
        E1_ONE(g4, d1.x);
        E1_ONE(g5, d1.y);
        E1_ONE(g6, d1.z);
        E1_ONE(g7, d1.w);
        #undef E1_ONE
    }
    GDC_LAUNCH();
}

// z = di^2 * a1, packed 8B; 2 nodes/thread; resets BN sums
__global__ void __launch_bounds__(256) k_node2() {
    int t = blockIdx.x * blockDim.x + threadIdx.x;
    int i0 = 2 * t, i1 = 2 * t + 1;
    bool a0 = (i0 < NN), b1 = (i1 < NN);
    float di0 = a0 ? d_dinv[i0] : 1.f;   // prelude (node1 is 2 kernels back)
    float di1 = b1 ? d_dinv[i1] : 1.f;
    GDC_WAIT();
    if (blockIdx.x == 0 && threadIdx.x < 4) {
        d_sum[threadIdx.x] = 0.0;
        d_sumsq[threadIdx.x] = 0.0;
    }
    float4 aa0 = a0 ? d_a1[i0] : make_float4(0, 0, 0, 0);
    float4 aa1 = b1 ? d_a1[i1] : make_float4(0, 0, 0, 0);
    if (a0) {
        float di2 = di0 * di0;
        half2 h01 = __floats2half2_rn(aa0.x * di2, aa0.y * di2);
        half2 h23 = __floats2half2_rn(aa0.z * di2, aa0.w * di2);
        float2 p;
        p.x = *reinterpret_cast<float*>(&h01);
        p.y = *reinterpret_cast<float*>(&h23);
        d_zp2[i0] = p;
    }
    if (b1) {
        float di2 = di1 * di1;
        half2 h01 = __floats2half2_rn(aa1.x * di2, aa1.y * di2);
        half2 h23 = __floats2half2_rn(aa1.z * di2, aa1.w * di2);
        float2 p;
        p.x = *reinterpret_cast<float*>(&h01);
        p.y = *reinterpret_cast<float*>(&h23);
        d_zp2[i1] = p;
    }
    GDC_LAUNCH();
}

// m[d] += z[s] (8B gathers); n-channel (extra dinv gathers) only when needn
__global__ void __launch_bounds__(256) k_edge2(const int* __restrict__ ei) {
    int t = blockIdx.x * blockDim.x + threadIdx.x;
    bool act = (t < NE / 8);
    int tt = act ? t : 0;
    const int4* sp = (const int4*)ei;
    const int4* dp = (const int4*)(ei + NE);
    int4 s0 = __ldg(&sp[2 * tt]), s1 = __ldg(&sp[2 * tt + 1]);
    int4 d0 = __ldg(&dp[2 * tt]), d1 = __ldg(&dp[2 * tt + 1]);
    GDC_WAIT();
    if (act) {
        int needn = d_needn;
        float2 g0 = __ldg(&d_zp2[s0.x]);
        float2 g1 = __ldg(&d_zp2[s0.y]);
        float2 g2 = __ldg(&d_zp2[s0.z]);
        float2 g3 = __ldg(&d_zp2[s0.w]);
        float2 g4 = __ldg(&d_zp2[s1.x]);
        float2 g5 = __ldg(&d_zp2[s1.y]);
        float2 g6 = __ldg(&d_zp2[s1.z]);
        float2 g7 = __ldg(&d_zp2[s1.w]);
        #define E2_ONE(g, dd) do {                                  \
            float4 _z = unpack8(g);                                 \
            red4(&d_m[dd], _z.x, _z.y, _z.z, _z.w);                 \
        } while (0)
        E2_ONE(g0, d0.x);
        E2_ONE(g1, d0.y);
        E2_ONE(g2, d0.z);
        E2_ONE(g3, d0.w);
        E2_ONE(g4, d1.x);
        E2_ONE(g5, d1.y);
        E2_ONE(g6, d1.z);
        E2_ONE(g7, d1.w);
        #undef E2_ONE
        if (needn) {   // rare path: conv1 bias nonzero
            red1(&d_n[d0.x], __ldg(&d_dinv[s0.x]));
            red1(&d_n[d0.y], __ldg(&d_dinv[s0.y]));
            red1(&d_n[d0.z], __ldg(&d_dinv[s0.z]));
            red1(&d_n[d0.w], __ldg(&d_dinv[s0.w]));
            red1(&d_n[d1.x], __ldg(&d_dinv[s1.x]));
            red1(&d_n[d1.y], __ldg(&d_dinv[s1.y]));
            red1(&d_n[d1.z], __ldg(&d_dinv[s1.z]));
            red1(&d_n[d1.w], __ldg(&d_dinv[s1.w]));
        }
    }
    GDC_LAUNCH();
}

// per-graph reduction; batch sorted → warp-uniform fast path; resets accumulators
#define NCOPY 8
__global__ void __launch_bounds__(256) k_node3(const int* __restrict__ batch) {
    __shared__ float sacc[NCOPY][NG * 6];
    for (int j = threadIdx.x; j < NCOPY * NG * 6; j += blockDim.x)
        ((float*)sacc)[j] = 0.f;
    __syncthreads();
    GDC_WAIT();
    int needn = d_needn;
    int w = (threadIdx.x >> 5) & (NCOPY - 1);
    int lane = threadIdx.x & 31;
    int stride = gridDim.x * blockDim.x;
    const float4 z4 = make_float4(0.f, 0.f, 0.f, 0.f);
    for (int i = blockIdx.x * blockDim.x + threadIdx.x; i < NN; i += stride) {
        float2 pz = d_zp2[i];
        float4 m = d_m[i];
        float di = d_dinv[i];
        int g = batch[i];
        d_m[i] = z4;
        d_degx[i] = 0.f;
        float4 z = unpack8(pz);
        float v0 = di * (m.x + z.x);
        float v1 = di * (m.y + z.y);
        float v2 = di * (m.z + z.z);
        float v3 = di * (m.w + z.w);
        float v4 = 0.f;
        if (needn) {
            float n = d_n[i];
            d_n[i] = 0.f;
            v4 = di * (n + di);
        }
        int g0 = __shfl_sync(0xffffffffu, g, 0);
        bool uniform = __all_sync(0xffffffffu, g == g0);
        if (uniform) {
            #pragma unroll
            for (int o = 16; o > 0; o >>= 1) {
                v0 += __shfl_down_sync(0xffffffffu, v0, o);
                v1 += __shfl_down_sync(0xffffffffu, v1, o);
                v2 += __shfl_down_sync(0xffffffffu, v2, o);
                v3 += __shfl_down_sync(0xffffffffu, v3, o);
                v4 += __shfl_down_sync(0xffffffffu, v4, o);
            }
            if (lane == 0) {
                float* pp = &sacc[w][g0 * 6];
                atomicAdd(pp + 0, v0);
                atomicAdd(pp + 1, v1);
                atomicAdd(pp + 2, v2);
                atomicAdd(pp + 3, v3);
                if (needn) atomicAdd(pp + 4, v4);
                atomicAdd(pp + 5, 32.0f);
            }
        } else {
            float* pp = &sacc[w][g * 6];
            atomicAdd(pp + 0, v0);
            atomicAdd(pp + 1, v1);
            atomicAdd(pp + 2, v2);
            atomicAdd(pp + 3, v3);
            if (needn) atomicAdd(pp + 4, v4);
            atomicAdd(pp + 5, 1.0f);
        }
    }
    __syncthreads();
    for (int j = threadIdx.x; j < NG * 6; j += blockDim.x) {
        float v = 0.f;
        #pragma unroll
        for (int k = 0; k < NCOPY; k++) v += sacc[k][j];
        int g = j / 6, c = j % 6;
        red1(&d_acc[g * 8 + c], v);
    }
    GDC_LAUNCH();
}

// Rank-7 tail: W0→W1→BN1→lin0→lin1→out as affine maps on the 7-vector
// c_g = (s4[0..3], ss, ng, 1). BN1 stats from the 7x7 second-moment matrix.
__global__ void __launch_bounds__(256) k_final(
        const float* __restrict__ W0, const float* __restrict__ b0,
        const float* __restrict__ W1, const float* __restrict__ b1,
        const float* __restrict__ bn1g, const float* __restrict__ bn1b,
        const float* __restrict__ l0W, const float* __restrict__ l0b,
        const float* __restrict__ l1W, const float* __restrict__ l1b,
        const float* __restrict__ oW, const float* __restrict__ ob,
        float* __restrict__ out) {
    __shared__ float sW[4096];
    __shared__ float sB[5][64];
    __shared__ float sA[2][7][68];
    __shared__ float sC[7][64];
    __shared__ float sS[7][7];
    __shared__ float swv[8];
    int t = threadIdx.x;

    for (int j = t; j < 4096; j += 256) sW[j] = W1[j];    // prelude
    if (t < 256) ((float*)sB)[t] = W0[t];
    if (t >= 192 && t < 256) sB[4][t - 192] = b0[t - 192];
    GDC_WAIT();

    if (t < 64) {
        float* acc = &d_acc[t * 8];
        sC[0][t] = acc[0];
        sC[1][t] = acc[1];
        sC[2][t] = acc[2];
        sC[3][t] = acc[3];
        sC[4][t] = acc[4];
        sC[5][t] = acc[5];
        sC[6][t] = 1.0f;
        #pragma unroll
        for (int c = 0; c < 8; c++) acc[c] = 0.f;
    }
    __syncthreads();

    for (int task = t; task < 320; task += 256) {
        int c = task >> 6, j = task & 63;
        float a = 0.f;
        #pragma unroll
        for (int k = 0; k < 64; k++) a += sB[c][k] * sW[k * 64 + j];
        sA[0][c][j] = a;
    }
    if (t < 64) {
        sA[0][5][t] = b1[t];
        sA[0][6][t] = 0.f;
    }
    if (t < 49) {
        int a = t / 7, b = t % 7;
        float s = 0.f;
        #pragma unroll
        for (int g = 0; g < 64; g++) s += sC[a][g] * sC[b][g];
        sS[a][b] = s;
    }
    __syncthreads();

    if (t < 64) {
        int j = t;
        float aj[7];
        #pragma unroll
        for (int c = 0; c < 7; c++) aj[c] = sA[0][c][j];
        float mu = 0.f;
        #pragma unroll
        for (int c = 0; c < 7; c++) mu += sS[c][6] * aj[c];
        mu *= (1.0f / 64.0f);
        float msq = 0.f;
        #pragma unroll
        for (int a = 0; a < 7; a++) {
            float inner = 0.f;
            #pragma unroll
            for (int b = 0; b < 7; b++) inner += sS[a][b] * aj[b];
            msq += aj[a] * inner;
        }
        msq *= (1.0f / 64.0f);
        float var = msq - mu * mu;
        float r = rsqrtf(var + EPS) * bn1g[j];
        #pragma unroll
        for (int c = 0; c < 7; c++) sA[0][c][j] = aj[c] * r;
        sA[0][6][j] += bn1b[j] - mu * r;
    }
    __syncthreads();

    for (int j = t; j < 4096; j += 256) sW[j] = l0W[j];
    __syncthreads();
    for (int task = t; task < 448; task += 256) {
        int c = task / 64, j = task & 63;
        float a = 0.f;
        #pragma unroll
        for (int k = 0; k < 64; k++) a += sA[0][c][k] * sW[k * 64 + j];
        if (c == 6) a += l0b[j];
        sA[1][c][j] = a;
    }
    __syncthreads();

    for (int j = t; j < 4096; j += 256) sW[j] = l1W[j];
    __syncthreads();
    for (int task = t; task < 448; task += 256) {
        int c = task / 64, j = task & 63;
        float a = 0.f;
        #pragma unroll
        for (int k = 0; k < 64; k++) a += sA[1][c][k] * sW[k * 64 + j];
        if (c == 6) a += l1b[j];
        sA[0][c][j] = a;
    }
    __syncthreads();

    if (t < 7) {
        float s = 0.f;
        #pragma unroll
        for (int j = 0; j < 64; j++) s += sA[0][t][j] * oW[j];
        swv[t] = s;
    }
    __syncthreads();
    if (t < 64) {
        float o = ob[0];
        #pragma unroll
        for (int c = 0; c < 7; c++) o += sC[c][t] * swv[c];
        out[t] = o;
    }
}

static void launch_pdl(const void* fn, dim3 grid, dim3 block, void** args) {
    cudaLaunchConfig_t cfg = {};
    cfg.gridDim = grid;
    cfg.blockDim = block;
    cfg.dynamicSmemBytes = 0;
    cfg.stream = 0;
    cudaLaunchAttribute at[1];
    at[0].id = cudaLaunchAttributeProgrammaticStreamSerialization;
    at[0].val.programmaticStreamSerializationAllowed = 1;
    cfg.attrs = at;
    cfg.numAttrs = 1;
    cudaLaunchKernelExC(&cfg, fn, args);
}

extern "C" void kernel_launch(void* const* d_in, const int* in_sizes, int n_in,
                              void* d_out, int out_size) {
    const float* x     = (const float*)d_in[0];
    const int*   ei    = (const int*)d_in[1];
    const int*   batch = (const int*)d_in[2];
    const float* bn0g = (const float*)d_in[3];
    const float* bn0b = (const float*)d_in[4];
    const float* W0   = (const float*)d_in[5];
    const float* b0   = (const float*)d_in[6];
    const float* W1   = (const float*)d_in[7];
    const float* b1   = (const float*)d_in[8];
    const float* bn1g = (const float*)d_in[9];
    const float* bn1b = (const float*)d_in[10];
    const float* l0W  = (const float*)d_in[11];
    const float* l0b  = (const float*)d_in[12];
    const float* l1W  = (const float*)d_in[13];
    const float* l1b  = (const float*)d_in[14];
    const float* oW   = (const float*)d_in[15];
    const float* ob   = (const float*)d_in[16];
    float* out = (float*)d_out;

    int et8 = NE / 8;
    dim3 b256(256);
    dim3 gE((et8 + 255) / 256);             // 1563
    dim3 gN2((NN / 2 + 255) / 256);         // 196

    { void* a[] = {(void*)&x, (void*)&ei};
      launch_pdl((const void*)k_pre, gE, b256, a); }
    { void* a[] = {(void*)&x, (void*)&bn0g, (void*)&bn0b, (void*)&b0};
      launch_pdl((const void*)k_node1, gN2, b256, a); }
    { void* a[] = {(void*)&ei};
      launch_pdl((const void*)k_edge1, gE, b256, a); }
    { void* a[] = {};
      launch_pdl((const void*)k_node2, gN2, b256, (void**)a); }
    { void* a[] = {(void*)&ei};
      launch_pdl((const void*)k_edge2, gE, b256, a); }
    { void* a[] = {(void*)&batch};
      launch_pdl((const void*)k_node3, dim3(296), b256, a); }
    { void* a[] = {(void*)&W0, (void*)&b0, (void*)&W1, (void*)&b1,
                   (void*)&bn1g, (void*)&bn1b, (void*)&l0W, (void*)&l0b,
                   (void*)&l1W, (void*)&l1b, (void*)&oW, (void*)&ob, (void*)&out};
      launch_pdl((const void*)k_final, dim3(1), b256, a); }
}